// round 2
// baseline (speedup 1.0000x reference)
#include <cuda_runtime.h>

#define N_CELLS 100000
#define N_ISO   16
#define KP1     31
#define WARPS_PER_BLOCK 8
#define THREADS (WARPS_PER_BLOCK * 32)

__device__ int g_idx_is64;

// Probe index dtype: int64 indices (values < 2^31) have zero upper words.
__global__ void probe_idx_kernel(const unsigned int* __restrict__ idx_raw) {
    int is64 = 1;
    #pragma unroll 1
    for (int k = 0; k < 64; k++) {
        unsigned int lo = idx_raw[2 * k];
        unsigned int hi = idx_raw[2 * k + 1];
        if (hi != 0u || lo >= (unsigned)N_CELLS) { is64 = 0; break; }
    }
    g_idx_is64 = is64;
}

__global__ void init_out_kernel(float* out) {
    out[0] = 0.0f;
}

__global__ __launch_bounds__(THREADS) void cost_kernel(
    const float* __restrict__ u,
    const float* __restrict__ s,
    const float* __restrict__ up,
    const float* __restrict__ sp,
    const void* __restrict__ idx_raw,
    float* __restrict__ out)
{
    const int warp = threadIdx.x >> 5;
    const int lane = threadIdx.x & 31;
    const int cell = blockIdx.x * WARPS_PER_BLOCK + warp;

    __shared__ float wsum[WARPS_PER_BLOCK];

    const int is64 = g_idx_is64;

    // Cell-own data: same address for all lanes -> L1 broadcast (free).
    const float ui = u[cell];
    const float uv = up[cell] - ui;

    const float4* s4  = reinterpret_cast<const float4*>(s  + (size_t)cell * N_ISO);
    const float4* sp4 = reinterpret_cast<const float4*>(sp + (size_t)cell * N_ISO);

    float si[N_ISO];
    float sv[N_ISO];
    #pragma unroll
    for (int q = 0; q < 4; q++) {
        float4 a = s4[q];
        float4 b = sp4[q];
        si[q*4+0] = a.x; si[q*4+1] = a.y; si[q*4+2] = a.z; si[q*4+3] = a.w;
        sv[q*4+0] = b.x - a.x; sv[q*4+1] = b.y - a.y;
        sv[q*4+2] = b.z - a.z; sv[q*4+3] = b.w - a.w;
    }

    float vsq = uv * uv;
    #pragma unroll
    for (int k = 0; k < N_ISO; k++) vsq = fmaf(sv[k], sv[k], vsq);
    const float vnorm = sqrtf(vsq);

    float cosv = -3.0e38f;  // lanes 30,31 contribute a tiny sentinel to the max
    if (lane < KP1 - 1) {
        // Coalesced: lanes 0..29 read consecutive neighbor indices.
        long long j;
        if (is64) {
            j = reinterpret_cast<const long long*>(idx_raw)[(size_t)cell * KP1 + 1 + lane];
        } else {
            j = (long long)reinterpret_cast<const int*>(idx_raw)[(size_t)cell * KP1 + 1 + lane];
        }
        // Safety clamp: a wrong-dtype read surfaces as rel_err, not a fault.
        if ((unsigned long long)j >= (unsigned long long)N_CELLS) j = 0;

        const float un = u[j] - ui;   // divergent gather (scalar)
        float dot = uv * un;
        float nsq = un * un;

        const float4* n4 = reinterpret_cast<const float4*>(s + (size_t)j * N_ISO);
        #pragma unroll
        for (int q = 0; q < 4; q++) {
            float4 a = n4[q];         // divergent gather (16B of 64B row)
            float d;
            d = a.x - si[q*4+0]; dot = fmaf(sv[q*4+0], d, dot); nsq = fmaf(d, d, nsq);
            d = a.y - si[q*4+1]; dot = fmaf(sv[q*4+1], d, dot); nsq = fmaf(d, d, nsq);
            d = a.z - si[q*4+2]; dot = fmaf(sv[q*4+2], d, dot); nsq = fmaf(d, d, nsq);
            d = a.w - si[q*4+3]; dot = fmaf(sv[q*4+3], d, dot); nsq = fmaf(d, d, nsq);
        }

        const float denom = vnorm * sqrtf(nsq);
        cosv = dot / (denom == 0.0f ? 1.0f : denom);
    }

    // Warp max-reduce over 30 cosines.
    #pragma unroll
    for (int o = 16; o > 0; o >>= 1)
        cosv = fmaxf(cosv, __shfl_xor_sync(0xffffffffu, cosv, o));

    const float cost = 1.0f - cosv;

    if (lane == 0) wsum[warp] = cost;
    __syncthreads();

    if (threadIdx.x == 0) {
        float sum = 0.0f;
        #pragma unroll
        for (int w = 0; w < WARPS_PER_BLOCK; w++) sum += wsum[w];
        atomicAdd(out, sum * (1.0f / (float)N_CELLS));
    }
}

extern "C" void kernel_launch(void* const* d_in, const int* in_sizes, int n_in,
                              void* d_out, int out_size) {
    const float* u    = (const float*)d_in[0];
    const float* s    = (const float*)d_in[1];
    const float* up   = (const float*)d_in[2];
    const float* sp   = (const float*)d_in[3];
    const void*  idxr = d_in[4];
    float* out = (float*)d_out;

    probe_idx_kernel<<<1, 1>>>((const unsigned int*)idxr);
    init_out_kernel<<<1, 1>>>(out);

    const int grid = N_CELLS / WARPS_PER_BLOCK;  // 12500, exact
    cost_kernel<<<grid, THREADS>>>(u, s, up, sp, idxr, out);
}

// round 3
// speedup vs baseline: 1.2798x; 1.2798x over previous
#include <cuda_runtime.h>

#define N_CELLS 100000
#define N_ISO   16
#define KP1     31
#define WARPS_PER_BLOCK 8
#define THREADS (WARPS_PER_BLOCK * 32)
#define GRID    1184
#define TOTAL_WARPS (GRID * WARPS_PER_BLOCK)

__device__ float        g_partials[GRID];
__device__ unsigned int g_ticket = 0;

__global__ __launch_bounds__(THREADS) void cost_kernel(
    const float* __restrict__ u,
    const float* __restrict__ s,
    const float* __restrict__ up,
    const float* __restrict__ sp,
    const int*   __restrict__ idx,
    float* __restrict__ out)
{
    const int warp    = threadIdx.x >> 5;
    const int lane    = threadIdx.x & 31;
    const int gwarp   = blockIdx.x * WARPS_PER_BLOCK + warp;
    const int chunk   = lane & 3;        // which 16B chunk of a row this lane loads
    const int nb_base = lane >> 2;       // neighbor sub-slot within a batch (0..7)

    __shared__ float ws[WARPS_PER_BLOCK];
    __shared__ int   s_islast;

    float lsum = 0.0f;

    for (int cell = gwarp; cell < N_CELLS; cell += TOTAL_WARPS) {
        // Cell-own data (same address across warp -> broadcast).
        const float ui = u[cell];
        const float uv = up[cell] - ui;

        const float4 a = reinterpret_cast<const float4*>(s  + (size_t)cell * N_ISO)[chunk];
        const float4 b = reinterpret_cast<const float4*>(sp + (size_t)cell * N_ISO)[chunk];
        const float sv0 = b.x - a.x, sv1 = b.y - a.y, sv2 = b.z - a.z, sv3 = b.w - a.w;

        // |v|^2 via quad-reduce of per-chunk partials.
        float pv = sv0*sv0 + sv1*sv1 + sv2*sv2 + sv3*sv3;
        pv += __shfl_xor_sync(0xffffffffu, pv, 1);
        pv += __shfl_xor_sync(0xffffffffu, pv, 2);
        const float vsq = fmaf(uv, uv, pv);

        // Coalesced neighbor index load (lanes 0..29).
        int my_idx = 0;
        if (lane < KP1 - 1) my_idx = idx[(size_t)cell * KP1 + 1 + lane];

        float cmax = -3.0e38f;

        #pragma unroll
        for (int bt = 0; bt < 4; bt++) {
            const int slot = bt * 8 + nb_base;                       // neighbor 0..31
            const int j    = __shfl_sync(0xffffffffu, my_idx, slot); // j=0 for slots 30,31 (masked below)

            // Cooperative gather: 32 lanes fetch 8 complete 64B rows -> 8 lines/LDG.
            const float4 nr = reinterpret_cast<const float4*>(s + (size_t)j * N_ISO)[chunk];
            const float d0 = nr.x - a.x, d1 = nr.y - a.y, d2 = nr.z - a.z, d3 = nr.w - a.w;

            float pdot = sv0*d0 + sv1*d1 + sv2*d2 + sv3*d3;
            float pnsq = d0*d0 + d1*d1 + d2*d2 + d3*d3;

            if (chunk == 0) {                     // quad leader handles the u component
                const float un = u[j] - ui;
                pdot = fmaf(uv, un, pdot);
                pnsq = fmaf(un, un, pnsq);
            }

            // Quad reduce (xor 1,2 stays within the aligned group of 4).
            pdot += __shfl_xor_sync(0xffffffffu, pdot, 1);
            pdot += __shfl_xor_sync(0xffffffffu, pdot, 2);
            pnsq += __shfl_xor_sync(0xffffffffu, pnsq, 1);
            pnsq += __shfl_xor_sync(0xffffffffu, pnsq, 2);

            if (chunk == 0 && slot < KP1 - 1) {
                const float den2 = vsq * pnsq;
                const float cosv = (den2 > 0.0f) ? pdot * rsqrtf(den2) : pdot;
                cmax = fmaxf(cmax, cosv);
            }
        }

        // Warp max over the 30 leader cosines.
        #pragma unroll
        for (int o = 16; o > 0; o >>= 1)
            cmax = fmaxf(cmax, __shfl_xor_sync(0xffffffffu, cmax, o));

        if (lane == 0) lsum += 1.0f - cmax;
    }

    if (lane == 0) ws[warp] = lsum;
    __syncthreads();

    if (threadIdx.x == 0) {
        float bsum = 0.0f;
        #pragma unroll
        for (int w = 0; w < WARPS_PER_BLOCK; w++) bsum += ws[w];
        g_partials[blockIdx.x] = bsum;
        __threadfence();
        // Wraps to 0 after GRID increments -> deterministic across graph replays.
        const unsigned t = atomicInc(&g_ticket, GRID - 1);
        s_islast = (t == GRID - 1);
    }
    __syncthreads();

    if (s_islast) {
        // Last block reduces all partials and writes the mean.
        float psum = 0.0f;
        const volatile float* vp = g_partials;
        for (int i = threadIdx.x; i < GRID; i += THREADS) psum += vp[i];
        #pragma unroll
        for (int o = 16; o > 0; o >>= 1)
            psum += __shfl_xor_sync(0xffffffffu, psum, o);
        if (lane == 0) ws[warp] = psum;
        __syncthreads();
        if (threadIdx.x == 0) {
            float total = 0.0f;
            #pragma unroll
            for (int w = 0; w < WARPS_PER_BLOCK; w++) total += ws[w];
            out[0] = total * (1.0f / (float)N_CELLS);
        }
    }
}

extern "C" void kernel_launch(void* const* d_in, const int* in_sizes, int n_in,
                              void* d_out, int out_size) {
    const float* u   = (const float*)d_in[0];
    const float* s   = (const float*)d_in[1];
    const float* up  = (const float*)d_in[2];
    const float* sp  = (const float*)d_in[3];
    const int*   idx = (const int*)d_in[4];
    float* out = (float*)d_out;

    cost_kernel<<<GRID, THREADS>>>(u, s, up, sp, idx, out);
}

// round 4
// speedup vs baseline: 1.5653x; 1.2231x over previous
#include <cuda_runtime.h>

#define N_CELLS 100000
#define N_ISO   16
#define KP1     31
#define WARPS_PER_BLOCK 8
#define THREADS (WARPS_PER_BLOCK * 32)
#define GRID    888                      /* 148 SMs x 6 blocks/SM -> exactly one wave */
#define TOTAL_WARPS (GRID * WARPS_PER_BLOCK)

__device__ float        g_partials[GRID];
__device__ unsigned int g_ticket = 0;

__global__ __launch_bounds__(THREADS, 6) void cost_kernel(
    const float* __restrict__ u,
    const float* __restrict__ s,
    const float* __restrict__ up,
    const float* __restrict__ sp,
    const int*   __restrict__ idx,
    float* __restrict__ out)
{
    const int warp    = threadIdx.x >> 5;
    const int lane    = threadIdx.x & 31;
    const int gwarp   = blockIdx.x * WARPS_PER_BLOCK + warp;
    const int chunk   = lane & 3;        // 16B chunk of a row this lane loads
    const int nb_base = lane >> 2;       // neighbor sub-slot within a batch (0..7)

    __shared__ float ws[WARPS_PER_BLOCK];
    __shared__ int   s_islast;

    float lsum = 0.0f;

    for (int cell = gwarp; cell < N_CELLS; cell += TOTAL_WARPS) {
        // Cell-own data (same address across warp -> broadcast).
        const float ui = u[cell];
        const float uv = up[cell] - ui;

        const float4 a = reinterpret_cast<const float4*>(s  + (size_t)cell * N_ISO)[chunk];
        const float4 b = reinterpret_cast<const float4*>(sp + (size_t)cell * N_ISO)[chunk];
        const float sv0 = b.x - a.x, sv1 = b.y - a.y, sv2 = b.z - a.z, sv3 = b.w - a.w;

        // |v|^2 via quad-reduce of per-chunk partials.
        float pv = sv0*sv0 + sv1*sv1 + sv2*sv2 + sv3*sv3;
        pv += __shfl_xor_sync(0xffffffffu, pv, 1);
        pv += __shfl_xor_sync(0xffffffffu, pv, 2);
        const float vsq = fmaf(uv, uv, pv);

        // Per-lane neighbor index + its u value, hoisted OUT of the batch loop.
        // idx load is coalesced; u gather overlaps the batch-0 s gathers.
        int   my_idx = 0;
        float my_un  = 0.0f;
        if (lane < KP1 - 1) {
            my_idx = idx[(size_t)cell * KP1 + 1 + lane];
            my_un  = u[my_idx] - ui;
        }

        float cmax = -3.0e38f;

        #pragma unroll
        for (int bt = 0; bt < 4; bt++) {
            const int   slot = bt * 8 + nb_base;                        // neighbor 0..31
            const int   j    = __shfl_sync(0xffffffffu, my_idx, slot);  // j=0 for 30,31 (masked)
            const float un   = __shfl_sync(0xffffffffu, my_un,  slot);  // off critical path now

            // Cooperative gather: 32 lanes fetch 8 complete 64B rows -> 8 lines/LDG.
            const float4 nr = reinterpret_cast<const float4*>(s + (size_t)j * N_ISO)[chunk];
            const float d0 = nr.x - a.x, d1 = nr.y - a.y, d2 = nr.z - a.z, d3 = nr.w - a.w;

            float pdot = sv0*d0 + sv1*d1 + sv2*d2 + sv3*d3;
            float pnsq = d0*d0 + d1*d1 + d2*d2 + d3*d3;

            // Quad reduce (xor 1,2 stays within the aligned group of 4).
            pdot += __shfl_xor_sync(0xffffffffu, pdot, 1);
            pdot += __shfl_xor_sync(0xffffffffu, pdot, 2);
            pnsq += __shfl_xor_sync(0xffffffffu, pnsq, 1);
            pnsq += __shfl_xor_sync(0xffffffffu, pnsq, 2);

            if (chunk == 0 && slot < KP1 - 1) {
                const float dot  = fmaf(uv, un, pdot);
                const float nsq  = fmaf(un, un, pnsq);
                const float den2 = vsq * nsq;
                const float cosv = (den2 > 0.0f) ? dot * rsqrtf(den2) : dot;
                cmax = fmaxf(cmax, cosv);
            }
        }

        // Warp max over the 30 leader cosines.
        #pragma unroll
        for (int o = 16; o > 0; o >>= 1)
            cmax = fmaxf(cmax, __shfl_xor_sync(0xffffffffu, cmax, o));

        if (lane == 0) lsum += 1.0f - cmax;
    }

    if (lane == 0) ws[warp] = lsum;
    __syncthreads();

    if (threadIdx.x == 0) {
        float bsum = 0.0f;
        #pragma unroll
        for (int w = 0; w < WARPS_PER_BLOCK; w++) bsum += ws[w];
        g_partials[blockIdx.x] = bsum;
        __threadfence();
        // Wraps to 0 after GRID increments -> deterministic across graph replays.
        const unsigned t = atomicInc(&g_ticket, GRID - 1);
        s_islast = (t == GRID - 1);
    }
    __syncthreads();

    if (s_islast) {
        float psum = 0.0f;
        const volatile float* vp = g_partials;
        for (int i = threadIdx.x; i < GRID; i += THREADS) psum += vp[i];
        #pragma unroll
        for (int o = 16; o > 0; o >>= 1)
            psum += __shfl_xor_sync(0xffffffffu, psum, o);
        if (lane == 0) ws[warp] = psum;
        __syncthreads();
        if (threadIdx.x == 0) {
            float total = 0.0f;
            #pragma unroll
            for (int w = 0; w < WARPS_PER_BLOCK; w++) total += ws[w];
            out[0] = total * (1.0f / (float)N_CELLS);
        }
    }
}

extern "C" void kernel_launch(void* const* d_in, const int* in_sizes, int n_in,
                              void* d_out, int out_size) {
    const float* u   = (const float*)d_in[0];
    const float* s   = (const float*)d_in[1];
    const float* up  = (const float*)d_in[2];
    const float* sp  = (const float*)d_in[3];
    const int*   idx = (const int*)d_in[4];
    float* out = (float*)d_out;

    cost_kernel<<<GRID, THREADS>>>(u, s, up, sp, idx, out);
}